// round 2
// baseline (speedup 1.0000x reference)
#include <cuda_runtime.h>
#include <cstdint>

#define N 8400
#define WORDS 132          // ceil(8400/64)
#define SCORE_THR 0.5f
#define IOU_THR 0.5f
#define ABLOCKS 33         // 33*256 = 8448 >= 8400
#define RCHUNK 4096        // rank SMEM chunk (32KB)

// ---- scratch (static device globals: allocation-free rule) ----
__device__ int g_vcount;                           // number of valid entries
__device__ unsigned long long g_vkey[N];           // compacted valid sort keys
__device__ float4 g_vbox[N];                       // compacted valid boxes
__device__ float g_vscore[N];                      // compacted valid scores
__device__ int g_rank[N];                          // rank among valid
__device__ float4 g_sbox[N];                       // sorted boxes (only [0,V) written)
__device__ float g_sscore[N];                      // sorted scores (only [0,V) written)
__device__ unsigned long long g_mask[N][WORDS];    // IoU suppression bitmask
__device__ unsigned long long g_remv[WORDS];       // final removed bits

// ---------------------------------------------------------------
// K0: reset the compaction counter (graph-replay deterministic).
// ---------------------------------------------------------------
__global__ void k_reset() {
    g_vcount = 0;
}

// ---------------------------------------------------------------
// K1: decode boxes + compact VALID entries (warp-aggregated atomic).
// Compaction order is arbitrary — ranking counts all pairs, so the final
// sorted order (and thus output) is deterministic regardless.
// key = (score_bits << 14) | (16383 - index): descending score, ascending
// index tie-break, unique.
// ---------------------------------------------------------------
__global__ void k_decode(const float* __restrict__ in) {
    int a = blockIdx.x * blockDim.x + threadIdx.x;
    int lane = threadIdx.x & 31;
    bool valid = false;
    float4 b = make_float4(0.f, 0.f, 0.f, 0.f);
    float s = 0.f;
    unsigned long long key = 0ull;
    if (a < N) {
        float cx = in[a];
        float cy = in[N + a];
        float w  = in[2 * N + a];
        float h  = in[3 * N + a];
        s = in[4 * N + a];
        float hw = __fmul_rn(w, 0.5f);
        float hh = __fmul_rn(h, 0.5f);
        b.x = __fsub_rn(cx, hw);
        b.y = __fsub_rn(cy, hh);
        b.z = __fadd_rn(cx, hw);
        b.w = __fadd_rn(cy, hh);
        valid = (s >= SCORE_THR);
        key = (((unsigned long long)__float_as_uint(s)) << 14)
            | (unsigned long long)(16383 - a);
    }
    unsigned m = __ballot_sync(0xffffffffu, valid);
    if (m == 0u) return;
    int leader = __ffs(m) - 1;
    int base = 0;
    if (lane == leader) base = atomicAdd(&g_vcount, __popc(m));
    base = __shfl_sync(0xffffffffu, base, leader);
    if (valid) {
        int pos = base + __popc(m & ((1u << lane) - 1u));
        g_vkey[pos]   = key;
        g_vbox[pos]   = b;
        g_vscore[pos] = s;
    }
}

// ---------------------------------------------------------------
// K2: rank among valid by counting (keys unique -> permutation of [0,V)).
// ---------------------------------------------------------------
__global__ void k_rank() {
    __shared__ unsigned long long sk[RCHUNK];
    int V = g_vcount;
    int p = blockIdx.x * blockDim.x + threadIdx.x;
    if (blockIdx.x * blockDim.x >= V) return;   // whole block idle: uniform exit
    unsigned long long kp = (p < V) ? g_vkey[p] : 0ull;
    int cnt = 0;
    for (int base = 0; base < V; base += RCHUNK) {
        int mlen = min(RCHUNK, V - base);
        __syncthreads();
        for (int d = threadIdx.x; d < mlen; d += blockDim.x)
            sk[d] = g_vkey[base + d];
        __syncthreads();
        if (p < V) {
#pragma unroll 8
            for (int d = 0; d < mlen; ++d)
                cnt += (sk[d] > kp) ? 1 : 0;
        }
    }
    if (p < V) g_rank[p] = cnt;
}

// ---------------------------------------------------------------
// K3: scatter into sorted order (valid only).
// ---------------------------------------------------------------
__global__ void k_scatter() {
    int V = g_vcount;
    int p = blockIdx.x * blockDim.x + threadIdx.x;
    if (p >= V) return;
    int r = g_rank[p];
    g_sbox[r]   = g_vbox[p];
    g_sscore[r] = g_vscore[p];
}

// ---------------------------------------------------------------
// K4: IoU suppression bitmask over the valid triangle only.
// No validity checks in the inner loop; diagonal tiles start at d = ti+1.
// All fp via _rn intrinsics (no FMA contraction) to bit-match XLA.
// ---------------------------------------------------------------
__global__ void k_mask() {
    int V = g_vcount;
    int Tv = (V + 63) >> 6;
    int rb = blockIdx.y, cb = blockIdx.x;
    if (cb < rb || cb >= Tv || rb >= Tv) return;   // uniform early exit
    __shared__ float4 cbox[64];
    __shared__ float carea[64];
    int t = threadIdx.x;   // 64 threads
    int j = cb * 64 + t;
    if (j < V) {
        float4 b = g_sbox[j];
        cbox[t] = b;
        carea[t] = __fmul_rn(__fsub_rn(b.z, b.x), __fsub_rn(b.w, b.y));
    } else {
        cbox[t] = make_float4(0.f, 0.f, 0.f, 0.f);  // zero box -> iou 0, no bit
        carea[t] = 0.f;
    }
    __syncthreads();
    int i = rb * 64 + t;
    if (i >= V) return;
    float4 bi = g_sbox[i];
    float ai = __fmul_rn(__fsub_rn(bi.z, bi.x), __fsub_rn(bi.w, bi.y));
    unsigned long long bits = 0ull;
    int dstart = (cb == rb) ? (t + 1) : 0;   // strict upper triangle
#pragma unroll 8
    for (int d = dstart; d < 64; ++d) {
        float4 bj = cbox[d];
        float ltx = fmaxf(bi.x, bj.x);
        float lty = fmaxf(bi.y, bj.y);
        float rbx = fminf(bi.z, bj.z);
        float rby = fminf(bi.w, bj.w);
        float wx = fmaxf(__fsub_rn(rbx, ltx), 0.0f);
        float wy = fmaxf(__fsub_rn(rby, lty), 0.0f);
        float inter = __fmul_rn(wx, wy);
        float uni = __fsub_rn(__fadd_rn(ai, carea[d]), inter);
        float iou = __fdiv_rn(inter, fmaxf(uni, 1e-9f));
        if (iou > IOU_THR) bits |= (1ull << d);
    }
    g_mask[i][cb] = bits;
}

// ---------------------------------------------------------------
// K5: greedy NMS reduce — ffs-driven scan (iterates kept bits only),
// then parallel OR of kept rows' mask words into future words.
// ---------------------------------------------------------------
__global__ void k_reduce() {
    __shared__ unsigned long long remv[WORDS];
    __shared__ unsigned long long diag[64];
    __shared__ int s_rows[64];
    __shared__ int s_nk;
    int tid = threadIdx.x;   // 256
    int V = g_vcount;
    int T = (V + 63) >> 6;
    for (int w = tid; w < WORDS; w += blockDim.x) remv[w] = 0ull;
    __syncthreads();

    for (int t = 0; t < T; ++t) {
        if (tid < 64) {
            int i = t * 64 + tid;
            diag[tid] = (i < V) ? g_mask[i][t] : 0ull;
        }
        __syncthreads();
        if (tid == 0) {
            unsigned long long cur = remv[t];
            int rem = V - t * 64;
            if (rem < 64) cur |= (~0ull) << rem;   // rows >= V: removed
            unsigned long long expl = cur;         // bits decided so far
            int nk = 0;
            while (~expl) {
                int b = __ffsll(~expl) - 1;        // lowest undecided zero = KEPT
                s_rows[nk++] = t * 64 + b;
                cur |= diag[b];                    // it suppresses later bits here
                expl = cur | ((2ull << b) - 1ull); // mark bits <= b decided
            }
            remv[t] = cur;
            s_nk = nk;
        }
        __syncthreads();
        int nk = s_nk;
        int nwords = T - 1 - t;
        int total = nk * nwords;
        for (int q = tid; q < total; q += blockDim.x) {
            int w = t + 1 + (q % nwords);
            int r = s_rows[q / nwords];
            unsigned long long m = g_mask[r][w];
            if (m) atomicOr(&remv[w], m);
        }
        __syncthreads();
    }

    for (int w = tid; w < WORDS; w += blockDim.x) g_remv[w] = remv[w];
}

// ---------------------------------------------------------------
// K6: emit output: kept -> [x1,y1,x2,y2,score], else zeros.
// For p >= V the box/score values are never used (kept=false).
// ---------------------------------------------------------------
__global__ void k_output(float* __restrict__ out) {
    int p = blockIdx.x * blockDim.x + threadIdx.x;
    if (p >= N) return;
    int V = g_vcount;
    bool kept = (p < V) && !((g_remv[p >> 6] >> (p & 63)) & 1ull);
    float4 b = kept ? g_sbox[p] : make_float4(0.f, 0.f, 0.f, 0.f);
    float s = kept ? g_sscore[p] : 0.f;
    out[p * 5 + 0] = b.x;
    out[p * 5 + 1] = b.y;
    out[p * 5 + 2] = b.z;
    out[p * 5 + 3] = b.w;
    out[p * 5 + 4] = s;
}

extern "C" void kernel_launch(void* const* d_in, const int* in_sizes, int n_in,
                              void* d_out, int out_size) {
    const float* in = (const float*)d_in[0];
    float* out = (float*)d_out;
    k_reset<<<1, 1>>>();
    k_decode<<<ABLOCKS, 256>>>(in);
    k_rank<<<ABLOCKS, 256>>>();
    k_scatter<<<ABLOCKS, 256>>>();
    k_mask<<<dim3(WORDS, WORDS), 64>>>();
    k_reduce<<<1, 256>>>();
    k_output<<<ABLOCKS, 256>>>(out);
}

// round 3
// speedup vs baseline: 1.2330x; 1.2330x over previous
#include <cuda_runtime.h>
#include <cstdint>

#define N 8400
#define WORDS 132          // ceil(8400/64)
#define SCORE_THR 0.5f
#define IOU_THR 0.5f
#define ABLOCKS 33         // 33*256 >= 8400
#define JS 8               // rank j-split
#define TB128 66           // ceil(8400/128)

typedef unsigned long long u64;

// ---- scratch (static device globals: allocation-free rule) ----
__device__ int g_vcount = 0;                 // reset by k_reduce_out each call
__device__ u64 g_vkey[N];
__device__ float4 g_vbox[N];
__device__ float g_vscore[N];
__device__ int g_rankp[JS][N];
__device__ float4 g_sbox[N];
__device__ float g_sscore[N];
__device__ u64 g_mask[N][WORDS];

// ---------------------------------------------------------------
// K1: decode + compact valid entries (warp-aggregated atomic).
// key = (score_bits << 14) | (16383 - index): unique, descending score,
// ascending-index tie-break. Compaction order irrelevant (rank is all-pairs).
// ---------------------------------------------------------------
__global__ void k_decode(const float* __restrict__ in) {
    int a = blockIdx.x * blockDim.x + threadIdx.x;
    int lane = threadIdx.x & 31;
    bool valid = false;
    float4 b = make_float4(0.f, 0.f, 0.f, 0.f);
    float s = 0.f;
    u64 key = 0ull;
    if (a < N) {
        float cx = in[a];
        float cy = in[N + a];
        float w  = in[2 * N + a];
        float h  = in[3 * N + a];
        s = in[4 * N + a];
        float hw = __fmul_rn(w, 0.5f);
        float hh = __fmul_rn(h, 0.5f);
        b.x = __fsub_rn(cx, hw);
        b.y = __fsub_rn(cy, hh);
        b.z = __fadd_rn(cx, hw);
        b.w = __fadd_rn(cy, hh);
        valid = (s >= SCORE_THR);
        key = (((u64)__float_as_uint(s)) << 14) | (u64)(16383 - a);
    }
    unsigned m = __ballot_sync(0xffffffffu, valid);
    if (m == 0u) return;
    int leader = __ffs(m) - 1;
    int base = 0;
    if (lane == leader) base = atomicAdd(&g_vcount, __popc(m));
    base = __shfl_sync(0xffffffffu, base, leader);
    if (valid) {
        int pos = base + __popc(m & ((1u << lane) - 1u));
        g_vkey[pos]   = key;
        g_vbox[pos]   = b;
        g_vscore[pos] = s;
    }
}

// ---------------------------------------------------------------
// K2: partial ranks — 2D grid (i-blocks x JS j-chunks) for full-chip spread.
// ---------------------------------------------------------------
__global__ void k_rank() {
    __shared__ u64 sk[1056];   // ceil(8400/8) = 1050
    int V = g_vcount;
    int ibase = blockIdx.x * 256;
    if (ibase >= V) return;    // uniform block exit before any sync
    int CH = (V + JS - 1) / JS;
    int jlo = blockIdx.y * CH;
    int jhi = min(jlo + CH, V);
    int mlen = jhi - jlo;      // may be <= 0; uniform across block
    for (int d = threadIdx.x; d < mlen; d += 256)
        sk[d] = g_vkey[jlo + d];
    __syncthreads();
    int p = ibase + threadIdx.x;
    u64 kp = (p < V) ? g_vkey[p] : 0ull;
    int cnt = 0;
#pragma unroll 8
    for (int d = 0; d < mlen; ++d)
        cnt += (sk[d] > kp) ? 1 : 0;
    if (p < V) g_rankp[blockIdx.y][p] = cnt;
}

// ---------------------------------------------------------------
// K3: sum partials + scatter into sorted order.
// ---------------------------------------------------------------
__global__ void k_scatter() {
    int V = g_vcount;
    int p = blockIdx.x * blockDim.x + threadIdx.x;
    if (p >= V) return;
    int r = 0;
#pragma unroll
    for (int y = 0; y < JS; ++y) r += g_rankp[y][p];
    g_sbox[r]   = g_vbox[p];
    g_sscore[r] = g_vscore[p];
}

// ---------------------------------------------------------------
// K4: IoU bitmask, 128x128 tiles, 256 threads (128 rows x 2 col-words).
// Guard-banded division screen: exact __fdiv_rn only when inter/den is
// within [0.4995, 0.5005] — outside the band the mul-compare decision is
// provably identical to the correctly-rounded division's.
// ---------------------------------------------------------------
__global__ void k_mask() {
    int V = g_vcount;
    int Tv = (V + 127) >> 7;
    int rb = blockIdx.y, cb = blockIdx.x;
    if (cb < rb || rb >= Tv || cb >= Tv) return;   // uniform early exit
    __shared__ float4 cbox[128];
    __shared__ float carea[128];
    int t = threadIdx.x;
    if (t < 128) {
        int j = cb * 128 + t;
        if (j < V) {
            float4 b = g_sbox[j];
            cbox[t] = b;
            carea[t] = __fmul_rn(__fsub_rn(b.z, b.x), __fsub_rn(b.w, b.y));
        } else {
            cbox[t] = make_float4(0.f, 0.f, 0.f, 0.f);  // zero box -> iou 0
            carea[t] = 0.f;
        }
    }
    __syncthreads();
    int row = t & 127;
    int half = t >> 7;
    int i = rb * 128 + row;
    if (i >= V) return;
    float4 bi = g_sbox[i];
    float ai = __fmul_rn(__fsub_rn(bi.z, bi.x), __fsub_rn(bi.w, bi.y));
    int cbase = half * 64;
    int wordbase = cb * 128 + cbase;
    int dstart = max(0, i + 1 - wordbase);   // strict upper triangle
    u64 bits = 0ull;
    for (int d = dstart; d < 64; ++d) {
        float4 bj = cbox[cbase + d];
        float ltx = fmaxf(bi.x, bj.x);
        float lty = fmaxf(bi.y, bj.y);
        float rbx = fminf(bi.z, bj.z);
        float rby = fminf(bi.w, bj.w);
        float wx = fmaxf(__fsub_rn(rbx, ltx), 0.0f);
        float wy = fmaxf(__fsub_rn(rby, lty), 0.0f);
        float inter = __fmul_rn(wx, wy);
        float uni = __fsub_rn(__fadd_rn(ai, carea[cbase + d]), inter);
        float den = fmaxf(uni, 1e-9f);
        bool hit;
        if (inter > __fmul_rn(0.5005f, den)) {
            hit = true;                       // ratio > 0.5005: rounded div > 0.5
        } else if (inter < __fmul_rn(0.4995f, den)) {
            hit = false;                      // ratio < 0.4995: rounded div < 0.5
        } else {
            hit = (__fdiv_rn(inter, den) > IOU_THR);  // borderline: exact
        }
        if (hit) bits |= (1ull << d);
    }
    g_mask[i][cb * 2 + half] = bits;
}

// ---------------------------------------------------------------
// K5: greedy reduce (1 block, ffs scan, double-buffered diag prefetch)
// fused with output emission and g_vcount reset.
// ---------------------------------------------------------------
__global__ void k_reduce_out(float* __restrict__ out) {
    __shared__ u64 remv[WORDS];
    __shared__ u64 diag[2][64];
    __shared__ int s_rows[64];
    __shared__ int s_nk;
    int tid = threadIdx.x;   // 256
    int V = g_vcount;
    int T = (V + 63) >> 6;
    for (int w = tid; w < WORDS; w += 256) remv[w] = 0ull;
    if (tid < 64) diag[0][tid] = (T > 0 && tid < V) ? g_mask[tid][0] : 0ull;
    __syncthreads();

    for (int t = 0; t < T; ++t) {
        int buf = t & 1;
        // prefetch next tile's diagonal concurrently with the scan
        if (tid >= 64 && tid < 128) {
            int tn = t + 1;
            u64 v = 0ull;
            if (tn < T) {
                int i = tn * 64 + (tid - 64);
                if (i < V) v = g_mask[i][tn];
            }
            diag[buf ^ 1][tid - 64] = v;
        }
        if (tid == 0) {
            u64 cur = remv[t];
            int rem = V - t * 64;
            if (rem < 64) cur |= (~0ull) << rem;   // rows >= V: removed
            u64 expl = cur;
            int nk = 0;
            while (~expl) {
                int b = __ffsll(~expl) - 1;        // lowest undecided bit = KEPT
                s_rows[nk++] = t * 64 + b;
                cur |= diag[buf][b];
                expl = cur | ((b == 63) ? ~0ull : ((2ull << b) - 1ull));
            }
            remv[t] = cur;
            s_nk = nk;
        }
        __syncthreads();
        int nk = s_nk;
        int nwords = T - 1 - t;
        int total = nk * nwords;
        for (int q = tid; q < total; q += 256) {
            int w = t + 1 + (q % nwords);
            int r = s_rows[q / nwords];
            u64 m = g_mask[r][w];
            if (m) atomicOr(&remv[w], m);
        }
        __syncthreads();
    }

    // fused output: kept -> [x1,y1,x2,y2,score], else zeros
    for (int p = tid; p < N; p += 256) {
        bool kept = (p < V) && !((remv[p >> 6] >> (p & 63)) & 1ull);
        float4 b = kept ? g_sbox[p] : make_float4(0.f, 0.f, 0.f, 0.f);
        float s = kept ? g_sscore[p] : 0.f;
        out[p * 5 + 0] = b.x;
        out[p * 5 + 1] = b.y;
        out[p * 5 + 2] = b.z;
        out[p * 5 + 3] = b.w;
        out[p * 5 + 4] = s;
    }
    if (tid == 0) g_vcount = 0;   // reset for the next (replayed) call
}

extern "C" void kernel_launch(void* const* d_in, const int* in_sizes, int n_in,
                              void* d_out, int out_size) {
    const float* in = (const float*)d_in[0];
    float* out = (float*)d_out;
    k_decode<<<ABLOCKS, 256>>>(in);
    k_rank<<<dim3(ABLOCKS, JS), 256>>>();
    k_scatter<<<ABLOCKS, 256>>>();
    k_mask<<<dim3(TB128, TB128), 256>>>();
    k_reduce_out<<<1, 256>>>(out);
}